// round 15
// baseline (speedup 1.0000x reference)
#include <cuda_runtime.h>
#include <cuda_fp16.h>
#include <math.h>

#define D 128
#define MAX_BN 100000
#define MAX_E  1600000
#define SCAN_B 512
#define FULL_MASK 0xFFFFFFFFu
#define AS_STRIDE 36     // 128 x 32 A chunk pad (conflict-free a-frag LDS)
#define WS_STRIDE 136    // 32 x 128 W chunk pad (conflict-free b-frag LDS)

// ---- scratch (allocation-free: __device__ globals) ----
__device__ __align__(16) __half g_h1[MAX_BN * D];    // xw1 (fp16)
__device__ __align__(16) __half g_h2[MAX_BN * D];    // xw2 (fp16)
__device__ __align__(16) float  g_bufB[MAX_BN * D];  // H (fp32)
__device__ __align__(16) float  g_bufC[MAX_BN * D];  // xres (fp32)
__device__ float g_deg[MAX_BN];
__device__ float g_dinv[MAX_BN];
__device__ int   g_cnt[MAX_BN];
__device__ int   g_cur[MAX_BN];
__device__ int   g_rs[MAX_BN + 1];    // CSR row_start by dst
__device__ int   g_srcs[MAX_E];       // src ids sorted by dst
__device__ float g_ws[MAX_E];         // weight sorted by dst, then coef in place
__device__ int   g_bsum[1024];        // scan block sums

// ---- helpers ----
__device__ __forceinline__ float gelu1(float x) {
    return 0.5f * x * (1.0f + erff(x * 0.7071067811865476f));
}

__device__ __forceinline__ unsigned cvt_tf32(float f) {
    unsigned u;
    asm("cvt.rna.tf32.f32 %0, %1;" : "=r"(u) : "f"(f));
    return u;
}

// ================= CSR construction =================
__global__ void zero_kernel(int BN) {
    int i = blockIdx.x * blockDim.x + threadIdx.x;
    if (i < BN) { g_cnt[i] = 0; g_cur[i] = 0; g_deg[i] = 1.0f; }
}

__global__ void hist_kernel(const int* __restrict__ dst, int E) {
    int e = blockIdx.x * blockDim.x + threadIdx.x;
    if (e < E) atomicAdd(&g_cnt[dst[e]], 1);
}

__global__ void __launch_bounds__(SCAN_B) scan_a_kernel(int BN) {
    __shared__ int s[SCAN_B];
    int t = threadIdx.x;
    int i = blockIdx.x * SCAN_B + t;
    int orig = (i < BN) ? g_cnt[i] : 0;
    s[t] = orig;
    __syncthreads();
#pragma unroll
    for (int off = 1; off < SCAN_B; off <<= 1) {
        int v = (t >= off) ? s[t - off] : 0;
        __syncthreads();
        s[t] += v;
        __syncthreads();
    }
    if (i < BN) g_rs[i] = s[t] - orig;
    if (t == SCAN_B - 1) g_bsum[blockIdx.x] = s[t];
}

__global__ void __launch_bounds__(SCAN_B) scan_b_kernel(int NB) {
    __shared__ int s[SCAN_B];
    int t = threadIdx.x;
    int orig = (t < NB) ? g_bsum[t] : 0;
    s[t] = orig;
    __syncthreads();
#pragma unroll
    for (int off = 1; off < SCAN_B; off <<= 1) {
        int v = (t >= off) ? s[t - off] : 0;
        __syncthreads();
        s[t] += v;
        __syncthreads();
    }
    if (t < NB) g_bsum[t] = s[t] - orig;
}

__global__ void scan_c_kernel(int BN, int E) {
    int i = blockIdx.x * blockDim.x + threadIdx.x;
    if (i < BN) g_rs[i] += g_bsum[i / SCAN_B];
    if (i == 0) g_rs[BN] = E;
}

__global__ void fill_kernel(const int* __restrict__ src,
                            const int* __restrict__ dst,
                            const float* __restrict__ ew, int E) {
    int e = blockIdx.x * blockDim.x + threadIdx.x;
    if (e < E) {
        int d = dst[e];
        float w = ew[e];
        int pos = atomicAdd(&g_cur[d], 1);
        int idx = g_rs[d] + pos;
        g_srcs[idx] = src[e];
        g_ws[idx]   = w;
        atomicAdd(&g_deg[d], w);
    }
}

__global__ void dinv_kernel(int BN) {
    int i = blockIdx.x * blockDim.x + threadIdx.x;
    if (i < BN) g_dinv[i] = rsqrtf(g_deg[i]);
}

__global__ void coef_kernel(int E) {
    int j = blockIdx.x * blockDim.x + threadIdx.x;
    if (j < E) g_ws[j] = g_dinv[g_srcs[j]] * g_ws[j];
}

// ================= tensor-core GEMM: C[M,128] = A[M,128] @ W[128,128] ========
// tf32 mma.sync m16n8k8. 256 thr = 8 warps (4m x 2n), block tile 128x128.
// HOUT: write fp16 (half2 packed); else fp32.
template <bool HOUT>
__global__ void __launch_bounds__(256) gemm_tc_kernel(
    const float* __restrict__ A, const float* __restrict__ W,
    void* __restrict__ Cv, int M)
{
    __shared__ __align__(16) unsigned As[128 * AS_STRIDE];
    __shared__ __align__(16) unsigned Ws[32 * WS_STRIDE];

    int t    = threadIdx.x;
    int lane = t & 31;
    int warp = t >> 5;
    int wm   = warp >> 1;
    int wn   = warp & 1;
    int g    = lane >> 2;
    int q    = lane & 3;
    int m0   = blockIdx.x * 128;

    float acc[2][8][4];
#pragma unroll
    for (int mf = 0; mf < 2; mf++)
#pragma unroll
        for (int nf = 0; nf < 8; nf++)
#pragma unroll
            for (int i = 0; i < 4; i++) acc[mf][nf][i] = 0.0f;

    for (int kc = 0; kc < 128; kc += 32) {
#pragma unroll
        for (int i = 0; i < 4; i++) {
            int f   = t + i * 256;
            int row = f >> 3;
            int c4  = f & 7;
            float4 v = make_float4(0.f, 0.f, 0.f, 0.f);
            if (m0 + row < M) v = ((const float4*)A)[(m0 + row) * 32 + (kc >> 2) + c4];
            unsigned* p = &As[row * AS_STRIDE + c4 * 4];
            p[0] = cvt_tf32(v.x); p[1] = cvt_tf32(v.y);
            p[2] = cvt_tf32(v.z); p[3] = cvt_tf32(v.w);
        }
#pragma unroll
        for (int i = 0; i < 4; i++) {
            int f  = t + i * 256;
            int kk = f >> 5;
            int n4 = f & 31;
            float4 v = ((const float4*)W)[(kc + kk) * 32 + n4];
            unsigned* p = &Ws[kk * WS_STRIDE + n4 * 4];
            p[0] = cvt_tf32(v.x); p[1] = cvt_tf32(v.y);
            p[2] = cvt_tf32(v.z); p[3] = cvt_tf32(v.w);
        }
        __syncthreads();

#pragma unroll
        for (int ks = 0; ks < 4; ks++) {
            int k = ks * 8;
            unsigned a[2][4];
#pragma unroll
            for (int mf = 0; mf < 2; mf++) {
                int mb = wm * 32 + mf * 16;
                a[mf][0] = As[(mb + g)     * AS_STRIDE + k + q];
                a[mf][1] = As[(mb + g + 8) * AS_STRIDE + k + q];
                a[mf][2] = As[(mb + g)     * AS_STRIDE + k + q + 4];
                a[mf][3] = As[(mb + g + 8) * AS_STRIDE + k + q + 4];
            }
#pragma unroll
            for (int nf = 0; nf < 8; nf++) {
                int nb = wn * 64 + nf * 8;
                unsigned b0 = Ws[(k + q)     * WS_STRIDE + nb + g];
                unsigned b1 = Ws[(k + q + 4) * WS_STRIDE + nb + g];
#pragma unroll
                for (int mf = 0; mf < 2; mf++) {
                    asm volatile(
                        "mma.sync.aligned.m16n8k8.row.col.f32.tf32.tf32.f32 "
                        "{%0,%1,%2,%3}, {%4,%5,%6,%7}, {%8,%9}, {%0,%1,%2,%3};"
                        : "+f"(acc[mf][nf][0]), "+f"(acc[mf][nf][1]),
                          "+f"(acc[mf][nf][2]), "+f"(acc[mf][nf][3])
                        : "r"(a[mf][0]), "r"(a[mf][1]),
                          "r"(a[mf][2]), "r"(a[mf][3]),
                          "r"(b0), "r"(b1));
                }
            }
        }
        __syncthreads();
    }

#pragma unroll
    for (int mf = 0; mf < 2; mf++) {
#pragma unroll
        for (int nf = 0; nf < 8; nf++) {
            int row = m0 + wm * 32 + mf * 16 + g;
            int col = wn * 64 + nf * 8 + q * 2;
            if (HOUT) {
                unsigned* C = (unsigned*)Cv;  // half2 lattice, 64 per row
                if (row < M) {
                    __half2 h = __floats2half2_rn(acc[mf][nf][0], acc[mf][nf][1]);
                    C[row * 64 + (col >> 1)] = *(unsigned*)&h;
                }
                if (row + 8 < M) {
                    __half2 h = __floats2half2_rn(acc[mf][nf][2], acc[mf][nf][3]);
                    C[(row + 8) * 64 + (col >> 1)] = *(unsigned*)&h;
                }
            } else {
                float* C = (float*)Cv;
                if (row < M)
                    *(float2*)&C[row * 128 + col] =
                        make_float2(acc[mf][nf][0], acc[mf][nf][1]);
                if (row + 8 < M)
                    *(float2*)&C[(row + 8) * 128 + col] =
                        make_float2(acc[mf][nf][2], acc[mf][nf][3]);
            }
        }
    }
}

// ================= fused gather + epilogue (fp16 features) =================
// Warp per dst node; lane owns 4 features (one uint2 = 4 halfs). fp32 accum.
template <bool L1>
__global__ void __launch_bounds__(256) gather_kernel(
    const __half* __restrict__ xw,    // [BN,128] fp16
    const float* __restrict__ bias,   // [128]
    const float* __restrict__ xres,   // [BN,128] (L1 only)
    const float* __restrict__ bres,   // [128]    (L1 only)
    float* __restrict__ out, int BN)
{
    int d    = (int)((blockIdx.x * 256u + threadIdx.x) >> 5);
    int lane = threadIdx.x & 31;
    if (d >= BN) return;

    const uint2* xh = (const uint2*)xw;   // 32 uint2 per row
    int s0 = g_rs[d], s1 = g_rs[d + 1];

    float4 acc = make_float4(0.f, 0.f, 0.f, 0.f);
    for (int j0 = s0; j0 < s1; j0 += 32) {
        int n = min(32, s1 - j0);
        int src = 0; float c = 0.0f;
        if (lane < n) {
            src = g_srcs[j0 + lane];
            c   = g_ws[j0 + lane];
        }
        int k = 0;
        for (; k + 4 <= n; k += 4) {
            int   i0 = __shfl_sync(FULL_MASK, src, k);
            int   i1 = __shfl_sync(FULL_MASK, src, k + 1);
            int   i2 = __shfl_sync(FULL_MASK, src, k + 2);
            int   i3 = __shfl_sync(FULL_MASK, src, k + 3);
            float c0 = __shfl_sync(FULL_MASK, c, k);
            float c1 = __shfl_sync(FULL_MASK, c, k + 1);
            float c2 = __shfl_sync(FULL_MASK, c, k + 2);
            float c3 = __shfl_sync(FULL_MASK, c, k + 3);
            uint2 u0 = xh[i0 * 32 + lane];
            uint2 u1 = xh[i1 * 32 + lane];
            uint2 u2 = xh[i2 * 32 + lane];
            uint2 u3 = xh[i3 * 32 + lane];
#define ACC_H(u, cc) do { \
            float2 f0 = __half22float2(*(__half2*)&(u).x); \
            float2 f1 = __half22float2(*(__half2*)&(u).y); \
            acc.x = fmaf(cc, f0.x, acc.x); acc.y = fmaf(cc, f0.y, acc.y); \
            acc.z = fmaf(cc, f1.x, acc.z); acc.w = fmaf(cc, f1.y, acc.w); } while (0)
            ACC_H(u0, c0); ACC_H(u1, c1); ACC_H(u2, c2); ACC_H(u3, c3);
        }
        for (; k < n; k++) {
            int   bs = __shfl_sync(FULL_MASK, src, k);
            float bc = __shfl_sync(FULL_MASK, c, k);
            uint2 u = xh[bs * 32 + lane];
            ACC_H(u, bc);
        }
#undef ACC_H
    }

    float dd = g_dinv[d];
    float s2 = dd * dd;
    uint2 su = xh[d * 32 + lane];
    float2 sf0 = __half22float2(*(__half2*)&su.x);
    float2 sf1 = __half22float2(*(__half2*)&su.y);
    float4 b = ((const float4*)bias)[lane];
    float4 r;
    r.x = fmaf(acc.x, dd, fmaf(sf0.x, s2, b.x));
    r.y = fmaf(acc.y, dd, fmaf(sf0.y, s2, b.y));
    r.z = fmaf(acc.z, dd, fmaf(sf1.x, s2, b.z));
    r.w = fmaf(acc.w, dd, fmaf(sf1.y, s2, b.w));

    float4 o;
    if (L1) {
        float4 xr = ((const float4*)xres)[d * 32 + lane];
        float4 br = ((const float4*)bres)[lane];
        o.x = gelu1(r.x) + 0.3f * (xr.x + br.x);
        o.y = gelu1(r.y) + 0.3f * (xr.y + br.y);
        o.z = gelu1(r.z) + 0.3f * (xr.z + br.z);
        o.w = gelu1(r.w) + 0.3f * (xr.w + br.w);
    } else {
        o.x = gelu1(r.x); o.y = gelu1(r.y);
        o.z = gelu1(r.z); o.w = gelu1(r.w);
    }
    ((float4*)out)[d * 32 + lane] = o;
}

extern "C" void kernel_launch(void* const* d_in, const int* in_sizes, int n_in,
                              void* d_out, int out_size)
{
    int s = (n_in >= 13) ? 0 : 2;
    const float* x    = (const float*)d_in[0];
    const int*   ei   = (const int*)d_in[1];     // int32 (JAX demotes int64)
    const float* ew   = (const float*)d_in[5 - s];
    const float* W1   = (const float*)d_in[7 - s];
    const float* b1   = (const float*)d_in[8 - s];
    const float* W2   = (const float*)d_in[9 - s];
    const float* b2   = (const float*)d_in[10 - s];
    const float* Wres = (const float*)d_in[11 - s];
    const float* bres = (const float*)d_in[12 - s];
    float*       out  = (float*)d_out;

    int BN = in_sizes[0] / D;
    int E  = in_sizes[1] / 2;

    __half *h1, *h2;
    float *bufB, *bufC;
    cudaGetSymbolAddress((void**)&h1, g_h1);
    cudaGetSymbolAddress((void**)&h2, g_h2);
    cudaGetSymbolAddress((void**)&bufB, g_bufB);
    cudaGetSymbolAddress((void**)&bufC, g_bufC);

    const int* src = ei;
    const int* dst = ei + E;

    int nbNode  = (BN + 255) / 256;
    int nbEdge  = (E + 255) / 256;
    int NB      = (BN + SCAN_B - 1) / SCAN_B;
    int nbWarpN = (BN + 7) / 8;
    int nbGemm  = (BN + 127) / 128;

    // ---- CSR by dst + normalization coefs (serial) ----
    zero_kernel<<<nbNode, 256>>>(BN);
    hist_kernel<<<nbEdge, 256>>>(dst, E);
    scan_a_kernel<<<NB, SCAN_B>>>(BN);
    scan_b_kernel<<<1, SCAN_B>>>(NB);
    scan_c_kernel<<<nbNode, 256>>>(BN, E);
    fill_kernel<<<nbEdge, 256>>>(src, dst, ew, E);   // also accumulates g_deg
    dinv_kernel<<<nbNode, 256>>>(BN);
    coef_kernel<<<nbEdge, 256>>>(E);

    // ---- layer 1 ----
    gemm_tc_kernel<true ><<<nbGemm, 256>>>(x, W1, h1, BN);     // xw1 (fp16)
    gemm_tc_kernel<false><<<nbGemm, 256>>>(x, Wres, bufC, BN); // xres (fp32)
    gather_kernel<true><<<nbWarpN, 256>>>(h1, b1, bufC, bres, bufB, BN); // H fp32

    // ---- layer 2 ----
    gemm_tc_kernel<true ><<<nbGemm, 256>>>(bufB, W2, h2, BN);  // xw2 (fp16)
    gather_kernel<false><<<nbWarpN, 256>>>(h2, b2, nullptr, nullptr, out, BN);
}

// round 17
// speedup vs baseline: 1.3688x; 1.3688x over previous
#include <cuda_runtime.h>
#include <math.h>

#define D 128
#define MAX_BN 100000
#define MAX_E  1600000
#define SCAN_B 512
#define FULL_MASK 0xFFFFFFFFu
#define AS_STRIDE 36     // 128 x 32 A chunk pad (conflict-free a-frag LDS)
#define WS_STRIDE 136    // 32 x 128 W chunk pad (conflict-free b-frag LDS)

// ---- scratch (allocation-free: __device__ globals) ----
__device__ __align__(16) float g_bufA[MAX_BN * D];   // xw1 / H
__device__ __align__(16) float g_bufB[MAX_BN * D];   // H / staging
__device__ __align__(16) float g_bufC[MAX_BN * D];   // xres / xw2
__device__ float g_deg[MAX_BN];
__device__ float g_dinv[MAX_BN];
__device__ int   g_cnt[MAX_BN];
__device__ int   g_cur[MAX_BN];
__device__ int   g_rs[MAX_BN + 1];    // CSR row_start by dst
__device__ int   g_srcs[MAX_E];       // src ids sorted by dst
__device__ float g_ws[MAX_E];         // weight sorted by dst, then coef in place
__device__ int   g_bsum[1024];        // scan block sums

// ---- helpers ----
__device__ __forceinline__ float gelu1(float x) {
    return 0.5f * x * (1.0f + erff(x * 0.7071067811865476f));
}

__device__ __forceinline__ unsigned cvt_tf32(float f) {
    unsigned u;
    asm("cvt.rna.tf32.f32 %0, %1;" : "=r"(u) : "f"(f));
    return u;
}

// ================= CSR construction =================
__global__ void zero_kernel(int BN) {
    int i = blockIdx.x * blockDim.x + threadIdx.x;
    if (i < BN) { g_cnt[i] = 0; g_cur[i] = 0; g_deg[i] = 1.0f; }
}

__global__ void hist_kernel(const int* __restrict__ dst, int E) {
    int e = blockIdx.x * blockDim.x + threadIdx.x;
    if (e < E) atomicAdd(&g_cnt[dst[e]], 1);
}

__global__ void __launch_bounds__(SCAN_B) scan_a_kernel(int BN) {
    __shared__ int s[SCAN_B];
    int t = threadIdx.x;
    int i = blockIdx.x * SCAN_B + t;
    int orig = (i < BN) ? g_cnt[i] : 0;
    s[t] = orig;
    __syncthreads();
#pragma unroll
    for (int off = 1; off < SCAN_B; off <<= 1) {
        int v = (t >= off) ? s[t - off] : 0;
        __syncthreads();
        s[t] += v;
        __syncthreads();
    }
    if (i < BN) g_rs[i] = s[t] - orig;
    if (t == SCAN_B - 1) g_bsum[blockIdx.x] = s[t];
}

__global__ void __launch_bounds__(SCAN_B) scan_b_kernel(int NB) {
    __shared__ int s[SCAN_B];
    int t = threadIdx.x;
    int orig = (t < NB) ? g_bsum[t] : 0;
    s[t] = orig;
    __syncthreads();
#pragma unroll
    for (int off = 1; off < SCAN_B; off <<= 1) {
        int v = (t >= off) ? s[t - off] : 0;
        __syncthreads();
        s[t] += v;
        __syncthreads();
    }
    if (t < NB) g_bsum[t] = s[t] - orig;
}

__global__ void scan_c_kernel(int BN, int E) {
    int i = blockIdx.x * blockDim.x + threadIdx.x;
    if (i < BN) g_rs[i] += g_bsum[i / SCAN_B];
    if (i == 0) g_rs[BN] = E;
}

__global__ void fill_kernel(const int* __restrict__ src,
                            const int* __restrict__ dst,
                            const float* __restrict__ ew, int E) {
    int e = blockIdx.x * blockDim.x + threadIdx.x;
    if (e < E) {
        int d = dst[e];
        float w = ew[e];
        int pos = atomicAdd(&g_cur[d], 1);
        int idx = g_rs[d] + pos;
        g_srcs[idx] = src[e];
        g_ws[idx]   = w;
        atomicAdd(&g_deg[d], w);
    }
}

__global__ void dinv_kernel(int BN) {
    int i = blockIdx.x * blockDim.x + threadIdx.x;
    if (i < BN) g_dinv[i] = rsqrtf(g_deg[i]);
}

__global__ void coef_kernel(int E) {
    int j = blockIdx.x * blockDim.x + threadIdx.x;
    if (j < E) g_ws[j] = g_dinv[g_srcs[j]] * g_ws[j];
}

// ================= tensor-core GEMM: C[M,128] = A[M,128] @ W[128,128] ========
// tf32 mma.sync m16n8k8. 256 thr = 8 warps (4m x 2n), block tile 128x128.
__global__ void __launch_bounds__(256) gemm_tc_kernel(
    const float* __restrict__ A, const float* __restrict__ W,
    float* __restrict__ C, int M)
{
    __shared__ __align__(16) unsigned As[128 * AS_STRIDE];
    __shared__ __align__(16) unsigned Ws[32 * WS_STRIDE];

    int t    = threadIdx.x;
    int lane = t & 31;
    int warp = t >> 5;
    int wm   = warp >> 1;
    int wn   = warp & 1;
    int g    = lane >> 2;
    int q    = lane & 3;
    int m0   = blockIdx.x * 128;

    float acc[2][8][4];
#pragma unroll
    for (int mf = 0; mf < 2; mf++)
#pragma unroll
        for (int nf = 0; nf < 8; nf++)
#pragma unroll
            for (int i = 0; i < 4; i++) acc[mf][nf][i] = 0.0f;

    for (int kc = 0; kc < 128; kc += 32) {
#pragma unroll
        for (int i = 0; i < 4; i++) {
            int f   = t + i * 256;
            int row = f >> 3;
            int c4  = f & 7;
            float4 v = make_float4(0.f, 0.f, 0.f, 0.f);
            if (m0 + row < M) v = ((const float4*)A)[(m0 + row) * 32 + (kc >> 2) + c4];
            unsigned* p = &As[row * AS_STRIDE + c4 * 4];
            p[0] = cvt_tf32(v.x); p[1] = cvt_tf32(v.y);
            p[2] = cvt_tf32(v.z); p[3] = cvt_tf32(v.w);
        }
#pragma unroll
        for (int i = 0; i < 4; i++) {
            int f  = t + i * 256;
            int kk = f >> 5;
            int n4 = f & 31;
            float4 v = ((const float4*)W)[(kc + kk) * 32 + n4];
            unsigned* p = &Ws[kk * WS_STRIDE + n4 * 4];
            p[0] = cvt_tf32(v.x); p[1] = cvt_tf32(v.y);
            p[2] = cvt_tf32(v.z); p[3] = cvt_tf32(v.w);
        }
        __syncthreads();

#pragma unroll
        for (int ks = 0; ks < 4; ks++) {
            int k = ks * 8;
            unsigned a[2][4];
#pragma unroll
            for (int mf = 0; mf < 2; mf++) {
                int mb = wm * 32 + mf * 16;
                a[mf][0] = As[(mb + g)     * AS_STRIDE + k + q];
                a[mf][1] = As[(mb + g + 8) * AS_STRIDE + k + q];
                a[mf][2] = As[(mb + g)     * AS_STRIDE + k + q + 4];
                a[mf][3] = As[(mb + g + 8) * AS_STRIDE + k + q + 4];
            }
#pragma unroll
            for (int nf = 0; nf < 8; nf++) {
                int nb = wn * 64 + nf * 8;
                unsigned b0 = Ws[(k + q)     * WS_STRIDE + nb + g];
                unsigned b1 = Ws[(k + q + 4) * WS_STRIDE + nb + g];
#pragma unroll
                for (int mf = 0; mf < 2; mf++) {
                    asm volatile(
                        "mma.sync.aligned.m16n8k8.row.col.f32.tf32.tf32.f32 "
                        "{%0,%1,%2,%3}, {%4,%5,%6,%7}, {%8,%9}, {%0,%1,%2,%3};"
                        : "+f"(acc[mf][nf][0]), "+f"(acc[mf][nf][1]),
                          "+f"(acc[mf][nf][2]), "+f"(acc[mf][nf][3])
                        : "r"(a[mf][0]), "r"(a[mf][1]),
                          "r"(a[mf][2]), "r"(a[mf][3]),
                          "r"(b0), "r"(b1));
                }
            }
        }
        __syncthreads();
    }

#pragma unroll
    for (int mf = 0; mf < 2; mf++) {
#pragma unroll
        for (int nf = 0; nf < 8; nf++) {
            int row = m0 + wm * 32 + mf * 16 + g;
            int col = wn * 64 + nf * 8 + q * 2;
            if (row < M)
                *(float2*)&C[row * 128 + col] =
                    make_float2(acc[mf][nf][0], acc[mf][nf][1]);
            if (row + 8 < M)
                *(float2*)&C[(row + 8) * 128 + col] =
                    make_float2(acc[mf][nf][2], acc[mf][nf][3]);
        }
    }
}

// ================= fused gather + epilogue =================
// Warp per dst node; lane owns one float4. Inner loop unrolled x4 (MLP).
template <bool L1>
__global__ void __launch_bounds__(256) gather_kernel(
    const float* __restrict__ xw,
    const float* __restrict__ bias,
    const float* __restrict__ xres,
    const float* __restrict__ bres,
    float* __restrict__ out, int BN)
{
    int d    = (int)((blockIdx.x * 256u + threadIdx.x) >> 5);
    int lane = threadIdx.x & 31;
    if (d >= BN) return;

    const float4* xw4 = (const float4*)xw;
    int s0 = g_rs[d], s1 = g_rs[d + 1];

    float4 acc = make_float4(0.f, 0.f, 0.f, 0.f);
    for (int j0 = s0; j0 < s1; j0 += 32) {
        int n = min(32, s1 - j0);
        int src = 0; float c = 0.0f;
        if (lane < n) {
            src = g_srcs[j0 + lane];
            c   = g_ws[j0 + lane];
        }
        int k = 0;
        for (; k + 4 <= n; k += 4) {
            int   s0i = __shfl_sync(FULL_MASK, src, k);
            int   s1i = __shfl_sync(FULL_MASK, src, k + 1);
            int   s2i = __shfl_sync(FULL_MASK, src, k + 2);
            int   s3i = __shfl_sync(FULL_MASK, src, k + 3);
            float c0  = __shfl_sync(FULL_MASK, c, k);
            float c1  = __shfl_sync(FULL_MASK, c, k + 1);
            float c2  = __shfl_sync(FULL_MASK, c, k + 2);
            float c3  = __shfl_sync(FULL_MASK, c, k + 3);
            float4 v0 = xw4[s0i * 32 + lane];
            float4 v1 = xw4[s1i * 32 + lane];
            float4 v2 = xw4[s2i * 32 + lane];
            float4 v3 = xw4[s3i * 32 + lane];
            acc.x = fmaf(c0, v0.x, acc.x); acc.y = fmaf(c0, v0.y, acc.y);
            acc.z = fmaf(c0, v0.z, acc.z); acc.w = fmaf(c0, v0.w, acc.w);
            acc.x = fmaf(c1, v1.x, acc.x); acc.y = fmaf(c1, v1.y, acc.y);
            acc.z = fmaf(c1, v1.z, acc.z); acc.w = fmaf(c1, v1.w, acc.w);
            acc.x = fmaf(c2, v2.x, acc.x); acc.y = fmaf(c2, v2.y, acc.y);
            acc.z = fmaf(c2, v2.z, acc.z); acc.w = fmaf(c2, v2.w, acc.w);
            acc.x = fmaf(c3, v3.x, acc.x); acc.y = fmaf(c3, v3.y, acc.y);
            acc.z = fmaf(c3, v3.z, acc.z); acc.w = fmaf(c3, v3.w, acc.w);
        }
        for (; k < n; k++) {
            int   bs = __shfl_sync(FULL_MASK, src, k);
            float bc = __shfl_sync(FULL_MASK, c, k);
            float4 v = xw4[bs * 32 + lane];
            acc.x = fmaf(bc, v.x, acc.x);
            acc.y = fmaf(bc, v.y, acc.y);
            acc.z = fmaf(bc, v.z, acc.z);
            acc.w = fmaf(bc, v.w, acc.w);
        }
    }

    float dd = g_dinv[d];
    float s2 = dd * dd;
    float4 self = xw4[d * 32 + lane];
    float4 b = ((const float4*)bias)[lane];
    float4 r;
    r.x = fmaf(acc.x, dd, fmaf(self.x, s2, b.x));
    r.y = fmaf(acc.y, dd, fmaf(self.y, s2, b.y));
    r.z = fmaf(acc.z, dd, fmaf(self.z, s2, b.z));
    r.w = fmaf(acc.w, dd, fmaf(self.w, s2, b.w));

    float4 o;
    if (L1) {
        float4 xr = ((const float4*)xres)[d * 32 + lane];
        float4 br = ((const float4*)bres)[lane];
        o.x = gelu1(r.x) + 0.3f * (xr.x + br.x);
        o.y = gelu1(r.y) + 0.3f * (xr.y + br.y);
        o.z = gelu1(r.z) + 0.3f * (xr.z + br.z);
        o.w = gelu1(r.w) + 0.3f * (xr.w + br.w);
    } else {
        o.x = gelu1(r.x); o.y = gelu1(r.y);
        o.z = gelu1(r.z); o.w = gelu1(r.w);
    }
    ((float4*)out)[d * 32 + lane] = o;
}

extern "C" void kernel_launch(void* const* d_in, const int* in_sizes, int n_in,
                              void* d_out, int out_size)
{
    int s = (n_in >= 13) ? 0 : 2;
    const float* x    = (const float*)d_in[0];
    const int*   ei   = (const int*)d_in[1];     // int32 (JAX demotes int64)
    const float* ew   = (const float*)d_in[5 - s];
    const float* W1   = (const float*)d_in[7 - s];
    const float* b1   = (const float*)d_in[8 - s];
    const float* W2   = (const float*)d_in[9 - s];
    const float* b2   = (const float*)d_in[10 - s];
    const float* Wres = (const float*)d_in[11 - s];
    const float* bres = (const float*)d_in[12 - s];
    float*       out  = (float*)d_out;

    int BN = in_sizes[0] / D;
    int E  = in_sizes[1] / 2;

    float *bufA, *bufB, *bufC;
    cudaGetSymbolAddress((void**)&bufA, g_bufA);
    cudaGetSymbolAddress((void**)&bufB, g_bufB);
    cudaGetSymbolAddress((void**)&bufC, g_bufC);

    const int* src = ei;
    const int* dst = ei + E;

    int nbNode  = (BN + 255) / 256;
    int nbEdge  = (E + 255) / 256;
    int NB      = (BN + SCAN_B - 1) / SCAN_B;
    int nbWarpN = (BN + 7) / 8;
    int nbGemm  = (BN + 127) / 128;

    // side stream + events (created once; identical captured work every call)
    static cudaStream_t s2 = nullptr;
    static cudaEvent_t  evFork = nullptr, evCSR = nullptr;
    if (s2 == nullptr) {
        cudaStreamCreateWithFlags(&s2, cudaStreamNonBlocking);
        cudaEventCreateWithFlags(&evFork, cudaEventDisableTiming);
        cudaEventCreateWithFlags(&evCSR, cudaEventDisableTiming);
    }

    // fork: CSR chain on side stream (isolated overlap test — single GEMMs
    // on the main stream, unlike the confounded R9 attempt)
    cudaEventRecord(evFork, 0);
    cudaStreamWaitEvent(s2, evFork, 0);
    zero_kernel<<<nbNode, 256, 0, s2>>>(BN);
    hist_kernel<<<nbEdge, 256, 0, s2>>>(dst, E);
    scan_a_kernel<<<NB, SCAN_B, 0, s2>>>(BN);
    scan_b_kernel<<<1, SCAN_B, 0, s2>>>(NB);
    scan_c_kernel<<<nbNode, 256, 0, s2>>>(BN, E);
    fill_kernel<<<nbEdge, 256, 0, s2>>>(src, dst, ew, E);   // also g_deg
    dinv_kernel<<<nbNode, 256, 0, s2>>>(BN);
    coef_kernel<<<nbEdge, 256, 0, s2>>>(E);
    cudaEventRecord(evCSR, s2);

    // main stream: the two independent layer-1 GEMMs (unchanged kernels)
    gemm_tc_kernel<<<nbGemm, 256>>>(x, W1, bufA, BN);       // xw1
    gemm_tc_kernel<<<nbGemm, 256>>>(x, Wres, bufC, BN);     // xres

    // join, then gather1 -> gemm2 -> gather2
    cudaStreamWaitEvent(0, evCSR, 0);
    gather_kernel<true><<<nbWarpN, 256>>>(bufA, b1, bufC, bres, bufB, BN); // H
    gemm_tc_kernel<<<nbGemm, 256>>>(bufB, W2, bufC, BN);    // xw2
    gather_kernel<false><<<nbWarpN, 256>>>(bufC, b2, nullptr, nullptr, out, BN);
}